// round 2
// baseline (speedup 1.0000x reference)
#include <cuda_runtime.h>

// ---------------- problem constants ----------------
#define NN    100000
#define EE    1600000
#define WIN   256
#define WH    64
#define NT    4
#define KHOP  10
#define ALPHAF 0.1f
#define MTOT  (NN*WH)          // 6,400,000
#define HB    (1<<22)          // histogram bins (1024 blocks * 4096)
#define HRANGE 12.0f           // hist covers [-12,12]
#define NB_STATS 391           // ceil(100000/256)
#define NSB   98               // ceil(100000/1024)

// ---------------- device scratch (static, no allocation) ----------------
__device__ float g_T [MTOT];   // tilde_H
__device__ float g_ZA[MTOT];   // H, then diffusion ping
__device__ float g_ZB[MTOT];   // diffusion pong (final)
__device__ float g_part[NB_STATS*512];
__device__ float g_mean[NT*WH], g_std[NT*WH], g_invs[NT*WH];
__device__ int   g_tcnt[NT];
__device__ int   g_cnt[NN];
__device__ int   g_rowptr[NN+1];
__device__ int   g_cursor[NN];
__device__ int   g_col[EE];
__device__ float g_coef[NN];
__device__ int   g_hist[HB];
__device__ int   g_bsum[1024], g_bsumex[1024];
__device__ long long g_babs[1024];
__device__ int   g_sb[128], g_sbex[128];

// ---------------- helpers ----------------
template<int BS>
__device__ __forceinline__ int blockScanInc(int v, int* sh) {
    int tid = threadIdx.x;
    sh[tid] = v; __syncthreads();
    #pragma unroll
    for (int off = 1; off < BS; off <<= 1) {
        int t = (tid >= off) ? sh[tid - off] : 0;
        __syncthreads();
        sh[tid] += t;
        __syncthreads();
    }
    return sh[tid];
}

template<int BS>
__device__ __forceinline__ int blockReduceInt(int v, int* sh) {
    int tid = threadIdx.x;
    sh[tid] = v; __syncthreads();
    #pragma unroll
    for (int off = BS/2; off > 0; off >>= 1) {
        if (tid < off) sh[tid] += sh[tid + off];
        __syncthreads();
    }
    return sh[0];
}

template<int BS>
__device__ __forceinline__ long long blockReduceLL(long long v, long long* sh) {
    int tid = threadIdx.x;
    sh[tid] = v; __syncthreads();
    #pragma unroll
    for (int off = BS/2; off > 0; off >>= 1) {
        if (tid < off) sh[tid] += sh[tid + off];
        __syncthreads();
    }
    return sh[0];
}

// ---------------- zero scratch that is accumulated into ----------------
__global__ void k_zero() {
    int i = blockIdx.x * blockDim.x + threadIdx.x;
    int stride = gridDim.x * blockDim.x;
    for (; i < HB; i += stride) {
        g_hist[i] = 0;
        if (i < NN) g_cnt[i] = 0;
        if (i < NT) g_tcnt[i] = 0;
    }
}

// ---------------- encode: H = l2norm_rows(X @ W + b) -> g_ZA ----------------
// block = 256 threads (8 warps), 32 rows/block, 4 rows/warp,
// lane computes output cols {2*lane, 2*lane+1}. W staged in smem in 2 K-halves.
__global__ void k_encode(const float* __restrict__ X,
                         const float* __restrict__ W,
                         const float* __restrict__ bvec) {
    __shared__ float Ws[128 * WH];   // 32 KB
    int tid  = threadIdx.x;
    int warp = tid >> 5, lane = tid & 31;
    int rowBase = blockIdx.x * 32 + warp * 4;

    float acc[4][2];
    #pragma unroll
    for (int r = 0; r < 4; r++) { acc[r][0] = 0.f; acc[r][1] = 0.f; }

    for (int half = 0; half < 2; half++) {
        for (int i = tid; i < 128 * WH; i += 256) Ws[i] = W[half * 128 * WH + i];
        __syncthreads();
        const float* x0 = X + (long)(rowBase + 0) * WIN + half * 128;
        const float* x1 = X + (long)(rowBase + 1) * WIN + half * 128;
        const float* x2 = X + (long)(rowBase + 2) * WIN + half * 128;
        const float* x3 = X + (long)(rowBase + 3) * WIN + half * 128;
        for (int kk = 0; kk < 128; kk += 32) {
            float xv0 = x0[kk + lane];
            float xv1 = x1[kk + lane];
            float xv2 = x2[kk + lane];
            float xv3 = x3[kk + lane];
            #pragma unroll
            for (int i = 0; i < 32; i++) {
                float2 w = *(const float2*)&Ws[(kk + i) * WH + lane * 2];
                float b0 = __shfl_sync(0xffffffffu, xv0, i);
                acc[0][0] += b0 * w.x; acc[0][1] += b0 * w.y;
                float b1 = __shfl_sync(0xffffffffu, xv1, i);
                acc[1][0] += b1 * w.x; acc[1][1] += b1 * w.y;
                float b2 = __shfl_sync(0xffffffffu, xv2, i);
                acc[2][0] += b2 * w.x; acc[2][1] += b2 * w.y;
                float b3 = __shfl_sync(0xffffffffu, xv3, i);
                acc[3][0] += b3 * w.x; acc[3][1] += b3 * w.y;
            }
        }
        __syncthreads();
    }

    float bb0 = bvec[lane * 2], bb1 = bvec[lane * 2 + 1];
    #pragma unroll
    for (int r = 0; r < 4; r++) {
        float v0 = acc[r][0] + bb0;
        float v1 = acc[r][1] + bb1;
        float ss = v0 * v0 + v1 * v1;
        #pragma unroll
        for (int o = 16; o > 0; o >>= 1) ss += __shfl_xor_sync(0xffffffffu, ss, o);
        float inv = 1.0f / fmaxf(sqrtf(ss), 1e-12f);
        int row = rowBase + r;
        g_ZA[row * WH + lane * 2]     = v0 * inv;
        g_ZA[row * WH + lane * 2 + 1] = v1 * inv;
    }
}

// ---------------- per-type counts ----------------
__global__ void k_typecount(const int* __restrict__ type) {
    __shared__ int c[NT];
    if (threadIdx.x < NT) c[threadIdx.x] = 0;
    __syncthreads();
    int i = blockIdx.x * blockDim.x + threadIdx.x;
    int stride = gridDim.x * blockDim.x;
    for (; i < NN; i += stride) atomicAdd(&c[type[i]], 1);
    __syncthreads();
    if (threadIdx.x < NT) atomicAdd(&g_tcnt[threadIdx.x], c[threadIdx.x]);
}

// ---------------- per-type sum / sumsq partials ----------------
// blockDim (64,4); 256 rows per block; writes deterministic block partials
__global__ void k_stats_partial(const int* __restrict__ type) {
    int f = threadIdx.x, yr = threadIdx.y;
    int r0 = blockIdx.x * 256;
    int rend = min(r0 + 256, NN);
    float s0=0,s1=0,s2=0,s3=0,q0=0,q1=0,q2=0,q3=0;
    for (int r = r0 + yr; r < rend; r += 4) {
        float v = g_ZA[r * WH + f];
        int t = type[r];
        float v2 = v * v;
        if      (t == 0) { s0 += v; q0 += v2; }
        else if (t == 1) { s1 += v; q1 += v2; }
        else if (t == 2) { s2 += v; q2 += v2; }
        else             { s3 += v; q3 += v2; }
    }
    __shared__ float sh[4][8][WH];
    sh[yr][0][f]=s0; sh[yr][1][f]=s1; sh[yr][2][f]=s2; sh[yr][3][f]=s3;
    sh[yr][4][f]=q0; sh[yr][5][f]=q1; sh[yr][6][f]=q2; sh[yr][7][f]=q3;
    __syncthreads();
    if (yr == 0) {
        #pragma unroll
        for (int s = 0; s < 8; s++) {
            float tot = sh[0][s][f] + sh[1][s][f] + sh[2][s][f] + sh[3][s][f];
            g_part[blockIdx.x * 512 + s * 64 + f] = tot;
        }
    }
}

// ---------------- finalize stats (deterministic fixed-order reduce) ----------------
__global__ void k_stats_final() {
    int idx = threadIdx.x;                 // t*64 + f, 0..255
    float S = 0.f, Q = 0.f;
    for (int b = 0; b < NB_STATS; b++) {
        S += g_part[b * 512 + idx];
        Q += g_part[b * 512 + 256 + idx];
    }
    float c = (float)g_tcnt[idx >> 6];
    float mean = S / c;
    float std  = (Q - c * mean * mean) / sqrtf(fmaxf(c - 1.0f, 1.0f));
    g_mean[idx] = mean;
    g_std[idx]  = std;
    g_invs[idx] = 1.0f / std;
}

// ---------------- whiten + embedding histogram (+1) ----------------
__global__ void k_tilde(const int* __restrict__ type) {
    const float invh = (float)HB / (2.0f * HRANGE);
    int i = blockIdx.x * blockDim.x + threadIdx.x;
    int stride = gridDim.x * blockDim.x;
    for (; i < MTOT; i += stride) {
        int row = i >> 6, f = i & 63;
        int t = type[row];
        float v = (g_ZA[i] - g_mean[t * WH + f]) * g_invs[t * WH + f];
        g_T[i] = v;
        int b = (int)((v + HRANGE) * invh);
        b = min(max(b, 0), HB - 1);
        atomicAdd(&g_hist[b], 1);
    }
}

// ---------------- gaussian sample histogram (-1) ----------------
__global__ void k_histg(const float* __restrict__ gs) {
    const float invh = (float)HB / (2.0f * HRANGE);
    int i = blockIdx.x * blockDim.x + threadIdx.x;
    int stride = gridDim.x * blockDim.x;
    for (; i < MTOT; i += stride) {
        float v = gs[i];
        int b = (int)((v + HRANGE) * invh);
        b = min(max(b, 0), HB - 1);
        atomicAdd(&g_hist[b], -1);
    }
}

// ---------------- degree counts ----------------
__global__ void k_cnt(const int* __restrict__ edge) {
    int i = blockIdx.x * blockDim.x + threadIdx.x;
    int stride = gridDim.x * blockDim.x;
    for (; i < EE; i += stride) atomicAdd(&g_cnt[edge[EE + i]], 1);
}

// ---------------- rowptr exclusive scan (3 kernels) ----------------
__global__ void k_scan1() {
    __shared__ int sh[1024];
    int i = blockIdx.x * 1024 + threadIdx.x;
    int v = (i < NN) ? g_cnt[i] : 0;
    int tot = blockReduceInt<1024>(v, sh);
    if (threadIdx.x == 0) g_sb[blockIdx.x] = tot;
}
__global__ void k_scan2() {
    __shared__ int sh[128];
    int v = (threadIdx.x < NSB) ? g_sb[threadIdx.x] : 0;
    int incl = blockScanInc<128>(v, sh);
    g_sbex[threadIdx.x] = incl - v;
}
__global__ void k_scan3() {
    __shared__ int sh[1024];
    int i = blockIdx.x * 1024 + threadIdx.x;
    int v = (i < NN) ? g_cnt[i] : 0;
    int incl = blockScanInc<1024>(v, sh);
    int total = g_sbex[blockIdx.x] + incl;
    if (i < NN) {
        g_rowptr[i + 1] = total;
        g_cursor[i]     = total - v;
        g_coef[i]       = (1.0f - ALPHAF) / fmaxf((float)v, 1.0f);
    }
    if (i == 0) g_rowptr[0] = 0;
}

// ---------------- CSR fill ----------------
__global__ void k_fill(const int* __restrict__ edge) {
    int i = blockIdx.x * blockDim.x + threadIdx.x;
    int stride = gridDim.x * blockDim.x;
    for (; i < EE; i += stride) {
        int src = edge[i];
        int dst = edge[EE + i];
        int p = atomicAdd(&g_cursor[dst], 1);
        g_col[p] = src;
    }
}

// ---------------- one PPR diffusion step ----------------
// blockDim (64,4): 4 rows per block, thread.x = feature column. Coalesced 256B
// row gathers from a 25.6MB Z buffer that lives in L2.
__global__ void k_diffuse(int it) {
    const float* Zin  = (it == 0) ? g_T : ((it & 1) ? g_ZA : g_ZB);
    float*       Zout = (it & 1) ? g_ZB : g_ZA;
    int row = blockIdx.x * 4 + threadIdx.y;
    int f = threadIdx.x;
    int beg = g_rowptr[row], end = g_rowptr[row + 1];
    float acc = 0.f;
    int e = beg;
    for (; e + 3 < end; e += 4) {
        int c0 = g_col[e], c1 = g_col[e+1], c2 = g_col[e+2], c3 = g_col[e+3];
        acc += Zin[c0*WH+f] + Zin[c1*WH+f] + Zin[c2*WH+f] + Zin[c3*WH+f];
    }
    for (; e < end; e++) acc += Zin[g_col[e]*WH + f];
    Zout[row*WH + f] = g_coef[row] * acc + ALPHAF * g_T[row*WH + f];
}

// ---------------- de-whiten + L2 normalize -> d_out ----------------
__global__ void k_final(const int* __restrict__ type, float* __restrict__ out) {
    int row = blockIdx.x * 4 + threadIdx.y;
    int f = threadIdx.x;
    int t = type[row];
    float v = g_ZB[row*WH + f] * g_std[t*WH + f] + g_mean[t*WH + f];
    float ss = v * v;
    #pragma unroll
    for (int o = 16; o > 0; o >>= 1) ss += __shfl_xor_sync(0xffffffffu, ss, o);
    __shared__ float sh2[4][2];
    int lane = threadIdx.x & 31, wh = threadIdx.x >> 5;
    if (lane == 0) sh2[threadIdx.y][wh] = ss;
    __syncthreads();
    float tot = sh2[threadIdx.y][0] + sh2[threadIdx.y][1];
    out[row*WH + f] = v / fmaxf(sqrtf(tot), 1e-12f);
}

// ---------------- W1 loss: Sum |prefix(hist)| * h / M (exact integer prefix) ----
__global__ void k_lossA() {
    __shared__ int sh[1024];
    int base = blockIdx.x * 4096 + threadIdx.x * 4;
    int s = g_hist[base] + g_hist[base+1] + g_hist[base+2] + g_hist[base+3];
    int tot = blockReduceInt<1024>(s, sh);
    if (threadIdx.x == 0) g_bsum[blockIdx.x] = tot;
}
__global__ void k_lossB() {
    __shared__ int sh[1024];
    int v = g_bsum[threadIdx.x];
    int incl = blockScanInc<1024>(v, sh);
    g_bsumex[threadIdx.x] = incl - v;
}
__global__ void k_lossC() {
    __shared__ int shs[1024];
    __shared__ long long shl[1024];
    int base = blockIdx.x * 4096 + threadIdx.x * 4;
    int h0 = g_hist[base], h1 = g_hist[base+1], h2 = g_hist[base+2], h3 = g_hist[base+3];
    int s = h0 + h1 + h2 + h3;
    int incl = blockScanInc<1024>(s, shs);
    int off = g_bsumex[blockIdx.x] + incl - s;
    int p1 = off + h0;
    int p2 = p1 + h1;
    int p3 = p2 + h2;
    int p4 = p3 + h3;
    long long a = (long long)abs(p1) + abs(p2) + abs(p3) + abs(p4);
    long long tot = blockReduceLL<1024>(a, shl);
    if (threadIdx.x == 0) g_babs[blockIdx.x] = tot;
}
__global__ void k_lossD(float* __restrict__ out, int out_size) {
    __shared__ long long shl[256];
    long long a = 0;
    for (int i = threadIdx.x; i < 1024; i += 256) a += g_babs[i];
    long long tot = blockReduceLL<256>(a, shl);
    if (threadIdx.x == 0 && out_size > MTOT) {
        double h = (2.0 * (double)HRANGE) / (double)HB;
        double loss = (double)tot * h / (double)MTOT;
        out[MTOT] = (float)loss;
    }
}

// ---------------- launcher ----------------
extern "C" void kernel_launch(void* const* d_in, const int* in_sizes, int n_in,
                              void* d_out, int out_size) {
    const float* X    = (const float*)d_in[0];
    const float* W    = (const float*)d_in[1];
    const float* bvec = (const float*)d_in[2];
    const float* gs   = (const float*)d_in[3];
    const int*   edge = (const int*)d_in[4];
    const int*   type = (const int*)d_in[5];
    float* out = (float*)d_out;

    k_zero<<<2048, 1024>>>();
    k_encode<<<NN / 32, 256>>>(X, W, bvec);
    k_typecount<<<391, 256>>>(type);
    k_stats_partial<<<NB_STATS, dim3(64, 4)>>>(type);
    k_stats_final<<<1, 256>>>();
    k_tilde<<<4096, 256>>>(type);
    k_histg<<<4096, 256>>>(gs);
    k_cnt<<<2048, 256>>>(edge);
    k_scan1<<<NSB, 1024>>>();
    k_scan2<<<1, 128>>>();
    k_scan3<<<NSB, 1024>>>();
    k_fill<<<2048, 256>>>(edge);
    for (int it = 0; it < KHOP; it++)
        k_diffuse<<<NN / 4, dim3(64, 4)>>>(it);
    k_final<<<NN / 4, dim3(64, 4)>>>(type, out);
    k_lossA<<<1024, 1024>>>();
    k_lossB<<<1, 1024>>>();
    k_lossC<<<1024, 1024>>>();
    k_lossD<<<1, 256>>>(out, out_size);
}

// round 3
// speedup vs baseline: 1.3217x; 1.3217x over previous
#include <cuda_runtime.h>

// ---------------- problem constants ----------------
#define NN    100000
#define EE    1600000
#define WIN   256
#define WH    64
#define NT    4
#define KHOP  10
#define ALPHAF 0.1f
#define MTOT  (NN*WH)          // 6,400,000
#define HB    (1<<20)          // histogram bins (256 blocks * 4096)
#define HBLK  256
#define HRANGE 12.0f           // hist covers [-12,12]
#define NB1   1024             // stats partial blocks
#define ROWS_PER_SB 98         // ceil(100000/1024)
#define NSB   98               // ceil(100000/1024) for rowptr scan

// ---------------- device scratch (static, no allocation) ----------------
__device__ float4 g_T4 [MTOT/4];   // tilde_H
__device__ float4 g_ZA4[MTOT/4];   // H, then diffusion ping
__device__ float4 g_ZB4[MTOT/4];   // diffusion pong (final)
__device__ float g_part[NB1*512];
__device__ float g_part2[32*512];
__device__ __align__(16) float g_mean[NT*WH];
__device__ __align__(16) float g_std [NT*WH];
__device__ __align__(16) float g_invs[NT*WH];
__device__ int   g_tcnt[NT];
__device__ int   g_cnt[NN];
__device__ int   g_rowptr[NN+1];
__device__ int   g_cursor[NN];
__device__ int   g_col[EE];
__device__ float g_coef[NN];
__device__ int   g_hist[HB];
__device__ int   g_bsum[HBLK], g_bsumex[HBLK];
__device__ long long g_babs[HBLK];
__device__ int   g_sb[128], g_sbex[128];

// ---------------- f32x2 packed helpers ----------------
__device__ __forceinline__ unsigned long long pk2(float a, float b) {
    unsigned long long r;
    asm("mov.b64 %0, {%1,%2};" : "=l"(r) : "f"(a), "f"(b));
    return r;
}
__device__ __forceinline__ void upk2(unsigned long long v, float& a, float& b) {
    asm("mov.b64 {%0,%1}, %2;" : "=f"(a), "=f"(b) : "l"(v));
}
__device__ __forceinline__ void fma2(unsigned long long& d, unsigned long long a,
                                     unsigned long long b) {
    asm("fma.rn.f32x2 %0, %1, %2, %3;" : "=l"(d) : "l"(a), "l"(b), "l"(d));
}

// ---------------- reduction helpers ----------------
template<int BS>
__device__ __forceinline__ int blockScanInc(int v, int* sh) {
    int tid = threadIdx.x;
    sh[tid] = v; __syncthreads();
    #pragma unroll
    for (int off = 1; off < BS; off <<= 1) {
        int t = (tid >= off) ? sh[tid - off] : 0;
        __syncthreads();
        sh[tid] += t;
        __syncthreads();
    }
    return sh[tid];
}
template<int BS>
__device__ __forceinline__ int blockReduceInt(int v, int* sh) {
    int tid = threadIdx.x;
    sh[tid] = v; __syncthreads();
    #pragma unroll
    for (int off = BS/2; off > 0; off >>= 1) {
        if (tid < off) sh[tid] += sh[tid + off];
        __syncthreads();
    }
    return sh[0];
}
template<int BS>
__device__ __forceinline__ long long blockReduceLL(long long v, long long* sh) {
    int tid = threadIdx.x;
    sh[tid] = v; __syncthreads();
    #pragma unroll
    for (int off = BS/2; off > 0; off >>= 1) {
        if (tid < off) sh[tid] += sh[tid + off];
        __syncthreads();
    }
    return sh[0];
}

// ---------------- zero scratch that is accumulated into ----------------
__global__ void k_zero() {
    int i = blockIdx.x * blockDim.x + threadIdx.x;
    int stride = gridDim.x * blockDim.x;
    for (; i < HB; i += stride) {
        g_hist[i] = 0;
        if (i < NN) g_cnt[i] = 0;
        if (i < NT) g_tcnt[i] = 0;
    }
}

// ---------------- encode: H = l2norm_rows(X @ W + b) -> g_ZA ----------------
// 64 rows x 64 cols per block, 256 threads. K split into 4 tiles of 64.
// X tile staged in smem pre-duplicated as {x,x} u64 so the inner loop is
// LDS.64 + FFMA2 (packed fp32x2 = 2 MACs/instr).
// thread: wgrp = tid>>5 owns rows wgrp*8..+7; colp = lane owns cols 2c,2c+1.
__global__ void __launch_bounds__(256) k_encode(const float* __restrict__ X,
                                                const float* __restrict__ W,
                                                const float* __restrict__ bvec) {
    __shared__ unsigned long long Xd[64][64];  // 32 KB, {x,x} duplicated
    __shared__ float Ws[64][64];               // 16 KB
    int tid  = threadIdx.x;
    int lane = tid & 31, wgrp = tid >> 5;
    int colp = lane;
    int rowBase = blockIdx.x * 64;
    int lr = tid >> 4, lc = tid & 15;          // loader coords

    unsigned long long acc[8];
    #pragma unroll
    for (int j = 0; j < 8; j++) acc[j] = 0ull;

    for (int q = 0; q < 4; q++) {
        #pragma unroll
        for (int rr = 0; rr < 64; rr += 16) {
            int row = rowBase + lr + rr;
            float4 xv = make_float4(0.f, 0.f, 0.f, 0.f);
            if (row < NN)
                xv = *(const float4*)&X[(size_t)row * WIN + q * 64 + lc * 4];
            Xd[lr + rr][lc * 4 + 0] = pk2(xv.x, xv.x);
            Xd[lr + rr][lc * 4 + 1] = pk2(xv.y, xv.y);
            Xd[lr + rr][lc * 4 + 2] = pk2(xv.z, xv.z);
            Xd[lr + rr][lc * 4 + 3] = pk2(xv.w, xv.w);
        }
        #pragma unroll
        for (int rr = 0; rr < 64; rr += 16)
            *(float4*)&Ws[lr + rr][lc * 4] =
                *(const float4*)&W[(size_t)(q * 64 + lr + rr) * WH + lc * 4];
        __syncthreads();

        #pragma unroll 4
        for (int k = 0; k < 64; k++) {
            unsigned long long w2 = *(const unsigned long long*)&Ws[k][colp * 2];
            #pragma unroll
            for (int j = 0; j < 8; j++)
                fma2(acc[j], Xd[wgrp * 8 + j][k], w2);
        }
        __syncthreads();
    }

    float bb0 = bvec[colp * 2], bb1 = bvec[colp * 2 + 1];
    float* ZA = (float*)g_ZA4;
    #pragma unroll
    for (int j = 0; j < 8; j++) {
        float v0, v1; upk2(acc[j], v0, v1);
        v0 += bb0; v1 += bb1;
        float ss = v0 * v0 + v1 * v1;
        #pragma unroll
        for (int o = 16; o > 0; o >>= 1) ss += __shfl_xor_sync(0xffffffffu, ss, o);
        float inv = 1.0f / fmaxf(sqrtf(ss), 1e-12f);
        int row = rowBase + wgrp * 8 + j;
        if (row < NN) {
            float2 out2; out2.x = v0 * inv; out2.y = v1 * inv;
            *(float2*)&ZA[(size_t)row * WH + colp * 2] = out2;
        }
    }
}

// ---------------- per-type counts ----------------
__global__ void k_typecount(const int* __restrict__ type) {
    __shared__ int c[NT];
    if (threadIdx.x < NT) c[threadIdx.x] = 0;
    __syncthreads();
    int i = blockIdx.x * blockDim.x + threadIdx.x;
    int stride = gridDim.x * blockDim.x;
    for (; i < NN; i += stride) atomicAdd(&c[type[i]], 1);
    __syncthreads();
    if (threadIdx.x < NT) atomicAdd(&g_tcnt[threadIdx.x], c[threadIdx.x]);
}

// ---------------- per-type sum / sumsq partials (deterministic) ----------------
__global__ void k_stats_partial(const int* __restrict__ type) {
    const float* ZA = (const float*)g_ZA4;
    int f = threadIdx.x, yr = threadIdx.y;
    int r0 = blockIdx.x * ROWS_PER_SB;
    int rend = min(r0 + ROWS_PER_SB, NN);
    float s0=0,s1=0,s2=0,s3=0,q0=0,q1=0,q2=0,q3=0;
    for (int r = r0 + yr; r < rend; r += 4) {
        float v = ZA[(size_t)r * WH + f];
        int t = type[r];
        float v2 = v * v;
        if      (t == 0) { s0 += v; q0 += v2; }
        else if (t == 1) { s1 += v; q1 += v2; }
        else if (t == 2) { s2 += v; q2 += v2; }
        else             { s3 += v; q3 += v2; }
    }
    __shared__ float sh[4][8][WH];
    sh[yr][0][f]=s0; sh[yr][1][f]=s1; sh[yr][2][f]=s2; sh[yr][3][f]=s3;
    sh[yr][4][f]=q0; sh[yr][5][f]=q1; sh[yr][6][f]=q2; sh[yr][7][f]=q3;
    __syncthreads();
    if (yr == 0) {
        #pragma unroll
        for (int s = 0; s < 8; s++) {
            float tot = sh[0][s][f] + sh[1][s][f] + sh[2][s][f] + sh[3][s][f];
            g_part[blockIdx.x * 512 + s * 64 + f] = tot;
        }
    }
}

// stage 2: 32 blocks x 512 threads; block b reduces partial-blocks [b*32,b*32+32)
__global__ void k_stats_mid() {
    int o = threadIdx.x;          // 0..511
    int b = blockIdx.x;           // 0..31
    float s = 0.f;
    #pragma unroll 8
    for (int j = 0; j < 32; j++)
        s += g_part[(b * 32 + j) * 512 + o];
    g_part2[b * 512 + o] = s;
}

// stage 3: finalize mean/std
__global__ void k_stats_final() {
    int idx = threadIdx.x;        // t*64 + f, 0..255
    float S = 0.f, Q = 0.f;
    #pragma unroll 8
    for (int b = 0; b < 32; b++) {
        S += g_part2[b * 512 + idx];
        Q += g_part2[b * 512 + 256 + idx];
    }
    float c = (float)g_tcnt[idx >> 6];
    float mean = S / c;
    float std  = (Q - c * mean * mean) / sqrtf(fmaxf(c - 1.0f, 1.0f));
    g_mean[idx] = mean;
    g_std[idx]  = std;
    g_invs[idx] = 1.0f / std;
}

// ---------------- whiten + embedding histogram (+1), float4 ----------------
__global__ void k_tilde(const int* __restrict__ type) {
    const float invh = (float)HB / (2.0f * HRANGE);
    int i = blockIdx.x * blockDim.x + threadIdx.x;   // over MTOT/4
    if (i >= MTOT/4) return;
    int row = i >> 4, f4 = i & 15;
    int t = type[row];
    float4 v = g_ZA4[i];
    float4 m = *(const float4*)&g_mean[t * WH + f4 * 4];
    float4 s = *(const float4*)&g_invs[t * WH + f4 * 4];
    float4 o;
    o.x = (v.x - m.x) * s.x;
    o.y = (v.y - m.y) * s.y;
    o.z = (v.z - m.z) * s.z;
    o.w = (v.w - m.w) * s.w;
    g_T4[i] = o;
    int b0 = min(max((int)((o.x + HRANGE) * invh), 0), HB - 1);
    int b1 = min(max((int)((o.y + HRANGE) * invh), 0), HB - 1);
    int b2 = min(max((int)((o.z + HRANGE) * invh), 0), HB - 1);
    int b3 = min(max((int)((o.w + HRANGE) * invh), 0), HB - 1);
    atomicAdd(&g_hist[b0], 1);
    atomicAdd(&g_hist[b1], 1);
    atomicAdd(&g_hist[b2], 1);
    atomicAdd(&g_hist[b3], 1);
}

// ---------------- gaussian sample histogram (-1), float4 ----------------
__global__ void k_histg(const float4* __restrict__ gs) {
    const float invh = (float)HB / (2.0f * HRANGE);
    int i = blockIdx.x * blockDim.x + threadIdx.x;
    if (i >= MTOT/4) return;
    float4 v = gs[i];
    int b0 = min(max((int)((v.x + HRANGE) * invh), 0), HB - 1);
    int b1 = min(max((int)((v.y + HRANGE) * invh), 0), HB - 1);
    int b2 = min(max((int)((v.z + HRANGE) * invh), 0), HB - 1);
    int b3 = min(max((int)((v.w + HRANGE) * invh), 0), HB - 1);
    atomicAdd(&g_hist[b0], -1);
    atomicAdd(&g_hist[b1], -1);
    atomicAdd(&g_hist[b2], -1);
    atomicAdd(&g_hist[b3], -1);
}

// ---------------- degree counts ----------------
__global__ void k_cnt(const int* __restrict__ edge) {
    int i = blockIdx.x * blockDim.x + threadIdx.x;
    int stride = gridDim.x * blockDim.x;
    for (; i < EE; i += stride) atomicAdd(&g_cnt[edge[EE + i]], 1);
}

// ---------------- rowptr exclusive scan (3 kernels) ----------------
__global__ void k_scan1() {
    __shared__ int sh[1024];
    int i = blockIdx.x * 1024 + threadIdx.x;
    int v = (i < NN) ? g_cnt[i] : 0;
    int tot = blockReduceInt<1024>(v, sh);
    if (threadIdx.x == 0) g_sb[blockIdx.x] = tot;
}
__global__ void k_scan2() {
    __shared__ int sh[128];
    int v = (threadIdx.x < NSB) ? g_sb[threadIdx.x] : 0;
    int incl = blockScanInc<128>(v, sh);
    g_sbex[threadIdx.x] = incl - v;
}
__global__ void k_scan3() {
    __shared__ int sh[1024];
    int i = blockIdx.x * 1024 + threadIdx.x;
    int v = (i < NN) ? g_cnt[i] : 0;
    int incl = blockScanInc<1024>(v, sh);
    int total = g_sbex[blockIdx.x] + incl;
    if (i < NN) {
        g_rowptr[i + 1] = total;
        g_cursor[i]     = total - v;
        g_coef[i]       = (1.0f - ALPHAF) / fmaxf((float)v, 1.0f);
    }
    if (i == 0) g_rowptr[0] = 0;
}

// ---------------- CSR fill ----------------
__global__ void k_fill(const int* __restrict__ edge) {
    int i = blockIdx.x * blockDim.x + threadIdx.x;
    int stride = gridDim.x * blockDim.x;
    for (; i < EE; i += stride) {
        int src = edge[i];
        int dst = edge[EE + i];
        int p = atomicAdd(&g_cursor[dst], 1);
        g_col[p] = src;
    }
}

// ---------------- one PPR diffusion step ----------------
// block (16,16): 16 rows per block, thread.x = float4 feature chunk.
// 8-deep unroll for MLP on the 16B gathers.
__global__ void __launch_bounds__(256) k_diffuse(int it) {
    const float4* Zin  = (it == 0) ? g_T4 : ((it & 1) ? g_ZA4 : g_ZB4);
    float4*       Zout = (it & 1) ? g_ZB4 : g_ZA4;
    int row = blockIdx.x * 16 + threadIdx.y;
    int f = threadIdx.x;   // 0..15
    int beg = g_rowptr[row], end = g_rowptr[row + 1];
    float4 a = make_float4(0.f, 0.f, 0.f, 0.f);
    int e = beg;
    for (; e + 8 <= end; e += 8) {
        int c[8];
        #pragma unroll
        for (int u = 0; u < 8; u++) c[u] = g_col[e + u];
        float4 v[8];
        #pragma unroll
        for (int u = 0; u < 8; u++) v[u] = Zin[c[u] * 16 + f];
        #pragma unroll
        for (int u = 0; u < 8; u++) {
            a.x += v[u].x; a.y += v[u].y; a.z += v[u].z; a.w += v[u].w;
        }
    }
    for (; e < end; e++) {
        float4 v = Zin[g_col[e] * 16 + f];
        a.x += v.x; a.y += v.y; a.z += v.z; a.w += v.w;
    }
    float cf = g_coef[row];
    float4 t = g_T4[row * 16 + f];
    float4 o;
    o.x = cf * a.x + ALPHAF * t.x;
    o.y = cf * a.y + ALPHAF * t.y;
    o.z = cf * a.z + ALPHAF * t.z;
    o.w = cf * a.w + ALPHAF * t.w;
    Zout[row * 16 + f] = o;
}

// ---------------- de-whiten + L2 normalize -> d_out ----------------
__global__ void k_final(const int* __restrict__ type, float* __restrict__ out) {
    const float* ZB = (const float*)g_ZB4;
    int row = blockIdx.x * 4 + threadIdx.y;
    int f = threadIdx.x;
    int t = type[row];
    float v = ZB[(size_t)row * WH + f] * g_std[t * WH + f] + g_mean[t * WH + f];
    float ss = v * v;
    #pragma unroll
    for (int o = 16; o > 0; o >>= 1) ss += __shfl_xor_sync(0xffffffffu, ss, o);
    __shared__ float sh2[4][2];
    int lane = threadIdx.x & 31, wh = threadIdx.x >> 5;
    if (lane == 0) sh2[threadIdx.y][wh] = ss;
    __syncthreads();
    float tot = sh2[threadIdx.y][0] + sh2[threadIdx.y][1];
    out[(size_t)row * WH + f] = v / fmaxf(sqrtf(tot), 1e-12f);
}

// ---------------- W1 loss: Sum |prefix(hist)| * h / M (exact integer prefix) ----
__global__ void k_lossA() {
    __shared__ int sh[1024];
    int base = blockIdx.x * 4096 + threadIdx.x * 4;
    int s = g_hist[base] + g_hist[base+1] + g_hist[base+2] + g_hist[base+3];
    int tot = blockReduceInt<1024>(s, sh);
    if (threadIdx.x == 0) g_bsum[blockIdx.x] = tot;
}
__global__ void k_lossB() {
    __shared__ int sh[HBLK];
    int v = g_bsum[threadIdx.x];
    int incl = blockScanInc<HBLK>(v, sh);
    g_bsumex[threadIdx.x] = incl - v;
}
__global__ void k_lossC() {
    __shared__ int shs[1024];
    __shared__ long long shl[1024];
    int base = blockIdx.x * 4096 + threadIdx.x * 4;
    int h0 = g_hist[base], h1 = g_hist[base+1], h2 = g_hist[base+2], h3 = g_hist[base+3];
    int s = h0 + h1 + h2 + h3;
    int incl = blockScanInc<1024>(s, shs);
    int off = g_bsumex[blockIdx.x] + incl - s;
    int p1 = off + h0;
    int p2 = p1 + h1;
    int p3 = p2 + h2;
    int p4 = p3 + h3;
    long long a = (long long)abs(p1) + abs(p2) + abs(p3) + abs(p4);
    long long tot = blockReduceLL<1024>(a, shl);
    if (threadIdx.x == 0) g_babs[blockIdx.x] = tot;
}
__global__ void k_lossD(float* __restrict__ out, int out_size) {
    __shared__ long long shl[256];
    long long a = 0;
    for (int i = threadIdx.x; i < HBLK; i += 256) a += g_babs[i];
    long long tot = blockReduceLL<256>(a, shl);
    if (threadIdx.x == 0 && out_size > MTOT) {
        double h = (2.0 * (double)HRANGE) / (double)HB;
        double loss = (double)tot * h / (double)MTOT;
        out[MTOT] = (float)loss;
    }
}

// ---------------- launcher ----------------
extern "C" void kernel_launch(void* const* d_in, const int* in_sizes, int n_in,
                              void* d_out, int out_size) {
    const float* X    = (const float*)d_in[0];
    const float* W    = (const float*)d_in[1];
    const float* bvec = (const float*)d_in[2];
    const float* gs   = (const float*)d_in[3];
    const int*   edge = (const int*)d_in[4];
    const int*   type = (const int*)d_in[5];
    float* out = (float*)d_out;

    k_zero<<<1024, 1024>>>();
    k_encode<<<(NN + 63) / 64, 256>>>(X, W, bvec);
    k_typecount<<<391, 256>>>(type);
    k_stats_partial<<<NB1, dim3(64, 4)>>>(type);
    k_stats_mid<<<32, 512>>>();
    k_stats_final<<<1, 256>>>();
    k_tilde<<<MTOT / 4 / 256, 256>>>(type);
    k_histg<<<MTOT / 4 / 256, 256>>>((const float4*)gs);
    k_cnt<<<2048, 256>>>(edge);
    k_scan1<<<NSB, 1024>>>();
    k_scan2<<<1, 128>>>();
    k_scan3<<<NSB, 1024>>>();
    k_fill<<<2048, 256>>>(edge);
    for (int it = 0; it < KHOP; it++)
        k_diffuse<<<NN / 16, dim3(16, 16)>>>(it);
    k_final<<<NN / 4, dim3(64, 4)>>>(type, out);
    k_lossA<<<HBLK, 1024>>>();
    k_lossB<<<1, HBLK>>>();
    k_lossC<<<HBLK, 1024>>>();
    k_lossD<<<1, 256>>>(out, out_size);
}